// round 2
// baseline (speedup 1.0000x reference)
#include <cuda_runtime.h>
#include <math.h>

#define NTOK 16384
#define NMASK 16383
#define CDIM 512
#define CFFD 2048

// ---------------- scratch (static device globals; no allocs) ----------------
__device__ float g_h[NTOK * CDIM];
__device__ float g_hn[NTOK * CDIM];
__device__ float g_qkv[NTOK * 3 * CDIM];
__device__ float g_attn[NTOK * CDIM];
__device__ float g_mlp[NTOK * CFFD];
__device__ float g_mod[6 * CDIM];
__device__ float g_siluc[CDIM];

// ---------------- input embed: h = feats@in_w.T + in_b + pos_embed ----------
__global__ void k_init(const float* __restrict__ feats, const int* __restrict__ coords,
                       const float* __restrict__ in_w, const float* __restrict__ in_b,
                       float* __restrict__ h) {
    int n = blockIdx.x;
    int tid = threadIdx.x;  // 256
    __shared__ float f[8];
    __shared__ int cd[3];
    if (tid < 8) f[tid] = feats[n * 8 + tid];
    if (tid < 3) cd[tid] = coords[n * 3 + tid];
    __syncthreads();
    for (int c = tid; c < CDIM; c += 256) {
        float acc = in_b[c];
#pragma unroll
        for (int i = 0; i < 8; i++) acc += f[i] * in_w[c * 8 + i];
        if (c < 510) {
            int j = c / 170;
            int k = c - j * 170;
            int kk = (k < 85) ? k : k - 85;
            float freq = expf((float)kk * (-9.210340371976184f / 85.0f));
            float o = (float)cd[j] * freq;
            acc += (k < 85) ? sinf(o) : cosf(o);
        }
        h[(long)n * CDIM + c] = acc;
    }
}

// ---------------- t embedding -> silu(c) ------------------------------------
__global__ void k_tembed(const float* __restrict__ t,
                         const float* __restrict__ w1, const float* __restrict__ b1,
                         const float* __restrict__ w2, const float* __restrict__ b2,
                         float* __restrict__ siluc) {
    __shared__ float emb[256];
    __shared__ float hid[512];
    int tid = threadIdx.x;  // 256
    float tv = t[0];
    if (tid < 128) {
        float fr = expf((float)tid * (-9.210340371976184f / 128.0f));
        float a = tv * fr;
        emb[tid] = cosf(a);
        emb[128 + tid] = sinf(a);
    }
    __syncthreads();
    for (int c = tid; c < 512; c += 256) {
        float acc = b1[c];
        const float* wr = w1 + (long)c * 256;
        for (int k = 0; k < 256; k++) acc += emb[k] * wr[k];
        hid[c] = acc / (1.0f + expf(-acc));  // silu
    }
    __syncthreads();
    for (int c = tid; c < 512; c += 256) {
        float acc = b2[c];
        const float* wr = w2 + (long)c * 512;
        for (int k = 0; k < 512; k++) acc += hid[k] * wr[k];
        siluc[c] = acc / (1.0f + expf(-acc));  // silu(c) used by adaLN
    }
}

// ---------------- adaLN modulation: mod = silu(c) @ ada_w.T + ada_b ---------
__global__ void k_ada(const float* __restrict__ siluc, const float* __restrict__ ada_w,
                      const float* __restrict__ ada_b, float* __restrict__ mod) {
    __shared__ float sc[512];
    int tid = threadIdx.x;  // 256 = 8 warps
    for (int c = tid; c < 512; c += 256) sc[c] = siluc[c];
    __syncthreads();
    int warp = tid >> 5, lane = tid & 31;
    int m = blockIdx.x * 8 + warp;  // grid 384 -> 3072 outputs
    const float* wr = ada_w + (long)m * 512;
    float acc = 0.f;
    for (int k = lane; k < 512; k += 32) acc += sc[k] * wr[k];
#pragma unroll
    for (int off = 16; off; off >>= 1) acc += __shfl_xor_sync(0xffffffffu, acc, off);
    if (lane == 0) mod[m] = acc + ada_b[m];
}

// ---------------- LN + modulation: hn = LN(h)*(1+sc) + sm -------------------
__global__ void k_modln(const float* __restrict__ h, float* __restrict__ hn,
                        const float* __restrict__ mod, int sc_off, int sm_off) {
    int n = blockIdx.x;
    int tid = threadIdx.x;  // 128
    const float4* hp = (const float4*)(h + (long)n * CDIM);
    float4 x = hp[tid];
    float s = x.x + x.y + x.z + x.w;
    float sq = x.x * x.x + x.y * x.y + x.z * x.z + x.w * x.w;
#pragma unroll
    for (int off = 16; off; off >>= 1) {
        s += __shfl_xor_sync(0xffffffffu, s, off);
        sq += __shfl_xor_sync(0xffffffffu, sq, off);
    }
    __shared__ float rs[4], rq[4];
    int warp = tid >> 5;
    if ((tid & 31) == 0) { rs[warp] = s; rq[warp] = sq; }
    __syncthreads();
    float S = rs[0] + rs[1] + rs[2] + rs[3];
    float SQ = rq[0] + rq[1] + rq[2] + rq[3];
    float mean = S * (1.0f / 512.0f);
    float var = SQ * (1.0f / 512.0f) - mean * mean;
    float inv = rsqrtf(var + 1e-6f);
    int c = tid * 4;
    float4 scv = *(const float4*)(mod + sc_off + c);
    float4 smv = *(const float4*)(mod + sm_off + c);
    float4 o;
    o.x = (x.x - mean) * inv * (1.0f + scv.x) + smv.x;
    o.y = (x.y - mean) * inv * (1.0f + scv.y) + smv.y;
    o.z = (x.z - mean) * inv * (1.0f + scv.z) + smv.z;
    o.w = (x.w - mean) * inv * (1.0f + scv.w) + smv.w;
    ((float4*)(hn + (long)n * CDIM))[tid] = o;
}

// ---------------- generic SGEMM: out(NxM) = A(NxK) @ W(MxK)^T [+ epilogue] --
// EPI 0: out = acc + bias
// EPI 1: out = gelu_tanh(acc + bias)
// EPI 2: dst += gate[col] * (acc + bias)   (dst==out, read-modify-write)
template <int EPI>
__global__ void __launch_bounds__(256, 2)
k_gemm(const float* __restrict__ A, const float* __restrict__ W,
       const float* __restrict__ bias, float* __restrict__ out,
       const float* __restrict__ gate, int K, int M) {
    __shared__ float As[8][128];
    __shared__ float Bs[8][128];
    int tid = threadIdx.x;
    int tx = tid & 15, ty = tid >> 4;
    int m0 = blockIdx.y * 128;  // row tile (N dim)
    int n0 = blockIdx.x * 128;  // col tile (M dim)
    float acc[8][8];
#pragma unroll
    for (int i = 0; i < 8; i++)
#pragma unroll
        for (int j = 0; j < 8; j++) acc[i][j] = 0.f;

    const float* Ap = A + (long)m0 * K;
    const float* Wp = W + (long)n0 * K;
    int lrow = tid >> 1;
    int lk = (tid & 1) * 4;

    for (int k0 = 0; k0 < K; k0 += 8) {
        float4 av = *(const float4*)(Ap + (long)lrow * K + k0 + lk);
        float4 bv = *(const float4*)(Wp + (long)lrow * K + k0 + lk);
        __syncthreads();
        As[lk + 0][lrow] = av.x; As[lk + 1][lrow] = av.y;
        As[lk + 2][lrow] = av.z; As[lk + 3][lrow] = av.w;
        Bs[lk + 0][lrow] = bv.x; Bs[lk + 1][lrow] = bv.y;
        Bs[lk + 2][lrow] = bv.z; Bs[lk + 3][lrow] = bv.w;
        __syncthreads();
#pragma unroll
        for (int k = 0; k < 8; k++) {
            float a[8], b[8];
            *(float4*)(a + 0) = *(const float4*)&As[k][4 * ty];
            *(float4*)(a + 4) = *(const float4*)&As[k][64 + 4 * ty];
            *(float4*)(b + 0) = *(const float4*)&Bs[k][4 * tx];
            *(float4*)(b + 4) = *(const float4*)&Bs[k][64 + 4 * tx];
#pragma unroll
            for (int i = 0; i < 8; i++)
#pragma unroll
                for (int j = 0; j < 8; j++) acc[i][j] += a[i] * b[j];
        }
    }

    // epilogue
    int cb[2] = {n0 + 4 * tx, n0 + 64 + 4 * tx};
    float bvv[8], gvv[8];
#pragma unroll
    for (int ch = 0; ch < 2; ch++)
#pragma unroll
        for (int jj = 0; jj < 4; jj++) {
            bvv[ch * 4 + jj] = __ldg(bias + cb[ch] + jj);
            if (EPI == 2) gvv[ch * 4 + jj] = __ldg(gate + cb[ch] + jj);
        }
    int rb[2] = {m0 + 4 * ty, m0 + 64 + 4 * ty};
#pragma unroll
    for (int rh = 0; rh < 2; rh++) {
#pragma unroll
        for (int ii = 0; ii < 4; ii++) {
            int r = rb[rh] + ii;
#pragma unroll
            for (int ch = 0; ch < 2; ch++) {
                float v[4];
#pragma unroll
                for (int jj = 0; jj < 4; jj++) {
                    float x = acc[rh * 4 + ii][ch * 4 + jj] + bvv[ch * 4 + jj];
                    if (EPI == 1) {
                        float x3 = x * x * x;
                        x = 0.5f * x * (1.0f + tanhf(0.7978845608028654f * (x + 0.044715f * x3)));
                    }
                    v[jj] = x;
                }
                float* dp = out + (long)r * M + cb[ch];
                if (EPI == 2) {
                    float4 oldv = *(float4*)dp;
                    float4 nv;
                    nv.x = oldv.x + gvv[ch * 4 + 0] * v[0];
                    nv.y = oldv.y + gvv[ch * 4 + 1] * v[1];
                    nv.z = oldv.z + gvv[ch * 4 + 2] * v[2];
                    nv.w = oldv.w + gvv[ch * 4 + 3] * v[3];
                    *(float4*)dp = nv;
                } else {
                    float4 nv = {v[0], v[1], v[2], v[3]};
                    *(float4*)dp = nv;
                }
            }
        }
    }
}

// ---------------- windowed flash attention ----------------------------------
// grid: (qtile=16, head=8, window=16), block 256 (16x16).
// Q tile 64 rows, KV tiles of 32, D=64. roll handled via index remap.
__global__ void __launch_bounds__(256)
k_attn(const float* __restrict__ qkv, float* __restrict__ attn, int shift) {
    __shared__ float Qt[64][68];  // [d][i], pre-scaled by 1/8
    __shared__ float Kt[64][36];  // [d][j]
    __shared__ float Vs[32][64];  // [j][d]
    __shared__ float Pt[32][68];  // [j][i]
    __shared__ float red[64][17];
    __shared__ float m_s[64], l_s[64], alpha_s[64];

    int tid = threadIdx.x;
    int tx = tid & 15, ty = tid >> 4;
    int qt = blockIdx.x, hh = blockIdx.y, w = blockIdx.z;
    int qbase = w * 1024 + qt * 64;

    // load Q tile (scaled)
    {
        int i = tid >> 2;
        int tok = (qbase + i + shift) & NMASK;
        const float* qp = qkv + (long)tok * 1536 + (hh << 6);
        int q0 = (tid & 3) * 4;
#pragma unroll
        for (int rep = 0; rep < 4; rep++) {
            int d0 = q0 + rep * 16;
            float4 v = *(const float4*)(qp + d0);
            Qt[d0 + 0][i] = 0.125f * v.x;
            Qt[d0 + 1][i] = 0.125f * v.y;
            Qt[d0 + 2][i] = 0.125f * v.z;
            Qt[d0 + 3][i] = 0.125f * v.w;
        }
    }
    if (tid < 64) { m_s[tid] = -1e30f; l_s[tid] = 0.f; }

    float o[4][4];
#pragma unroll
    for (int i = 0; i < 4; i++)
#pragma unroll
        for (int j = 0; j < 4; j++) o[i][j] = 0.f;

    for (int j0 = 0; j0 < 1024; j0 += 32) {
        // global loads into regs
        int jr = tid >> 3;
        int tok = (w * 1024 + j0 + jr + shift) & NMASK;
        const float* kp = qkv + (long)tok * 1536 + 512 + (hh << 6);
        const float* vp = kp + 512;
        int d0 = (tid & 7) * 4;
        float4 ka = *(const float4*)(kp + d0);
        float4 kb = *(const float4*)(kp + d0 + 32);
        float4 va = *(const float4*)(vp + d0);
        float4 vb = *(const float4*)(vp + d0 + 32);

        __syncthreads();  // previous tile consumed
        Kt[d0 + 0][jr] = ka.x; Kt[d0 + 1][jr] = ka.y;
        Kt[d0 + 2][jr] = ka.z; Kt[d0 + 3][jr] = ka.w;
        Kt[d0 + 32][jr] = kb.x; Kt[d0 + 33][jr] = kb.y;
        Kt[d0 + 34][jr] = kb.z; Kt[d0 + 35][jr] = kb.w;
        *(float4*)&Vs[jr][d0] = va;
        *(float4*)&Vs[jr][d0 + 32] = vb;
        __syncthreads();

        // S = Q K^T (rows 4ty+ii, cols 2tx+jj)
        float s0[4][2];
#pragma unroll
        for (int i = 0; i < 4; i++) { s0[i][0] = 0.f; s0[i][1] = 0.f; }
#pragma unroll
        for (int d = 0; d < 64; d++) {
            float4 qv = *(const float4*)&Qt[d][4 * ty];
            float k0v = Kt[d][2 * tx], k1v = Kt[d][2 * tx + 1];
            s0[0][0] += qv.x * k0v; s0[0][1] += qv.x * k1v;
            s0[1][0] += qv.y * k0v; s0[1][1] += qv.y * k1v;
            s0[2][0] += qv.z * k0v; s0[2][1] += qv.z * k1v;
            s0[3][0] += qv.w * k0v; s0[3][1] += qv.w * k1v;
        }

        // row max
#pragma unroll
        for (int ii = 0; ii < 4; ii++)
            red[4 * ty + ii][tx] = fmaxf(s0[ii][0], s0[ii][1]);
        __syncthreads();
        if (tid < 64) {
            float mx = red[tid][0];
#pragma unroll
            for (int x = 1; x < 16; x++) mx = fmaxf(mx, red[tid][x]);
            float mo = m_s[tid];
            float mn = fmaxf(mo, mx);
            m_s[tid] = mn;
            alpha_s[tid] = __expf(mo - mn);
        }
        __syncthreads();

        // p = exp(s - m), rescale o, store P^T, partial row sums
#pragma unroll
        for (int ii = 0; ii < 4; ii++) {
            int r = 4 * ty + ii;
            float mn = m_s[r];
            float a = alpha_s[r];
            float p0 = __expf(s0[ii][0] - mn);
            float p1 = __expf(s0[ii][1] - mn);
            o[ii][0] *= a; o[ii][1] *= a; o[ii][2] *= a; o[ii][3] *= a;
            Pt[2 * tx + 0][r] = p0;
            Pt[2 * tx + 1][r] = p1;
            red[r][tx] = p0 + p1;
        }
        __syncthreads();
        if (tid < 64) {
            float sm = 0.f;
#pragma unroll
            for (int x = 0; x < 16; x++) sm += red[tid][x];
            l_s[tid] = l_s[tid] * alpha_s[tid] + sm;
        }

        // O += P V (no extra sync needed: Pt/Vs stable until top-of-loop sync)
#pragma unroll 8
        for (int j = 0; j < 32; j++) {
            float4 pv = *(const float4*)&Pt[j][4 * ty];
            float4 vv = *(const float4*)&Vs[j][4 * tx];
            o[0][0] += pv.x * vv.x; o[0][1] += pv.x * vv.y; o[0][2] += pv.x * vv.z; o[0][3] += pv.x * vv.w;
            o[1][0] += pv.y * vv.x; o[1][1] += pv.y * vv.y; o[1][2] += pv.y * vv.z; o[1][3] += pv.y * vv.w;
            o[2][0] += pv.z * vv.x; o[2][1] += pv.z * vv.y; o[2][2] += pv.z * vv.z; o[2][3] += pv.z * vv.w;
            o[3][0] += pv.w * vv.x; o[3][1] += pv.w * vv.y; o[3][2] += pv.w * vv.z; o[3][3] += pv.w * vv.w;
        }
    }
    __syncthreads();

#pragma unroll
    for (int ii = 0; ii < 4; ii++) {
        int r = 4 * ty + ii;
        float inv = 1.0f / l_s[r];
        int tok = (qbase + r + shift) & NMASK;
        float4 res;
        res.x = o[ii][0] * inv; res.y = o[ii][1] * inv;
        res.z = o[ii][2] * inv; res.w = o[ii][3] * inv;
        *(float4*)(attn + (long)tok * CDIM + (hh << 6) + 4 * tx) = res;
    }
}

// ---------------- output head: out = h @ out_w.T + out_b --------------------
__global__ void k_final(const float* __restrict__ h, const float* __restrict__ out_w,
                        const float* __restrict__ out_b, float* __restrict__ out) {
    int warp = threadIdx.x >> 5, lane = threadIdx.x & 31;
    int n = blockIdx.x * 8 + warp;
    const float* hp = h + (long)n * CDIM;
    float acc[8];
#pragma unroll
    for (int o = 0; o < 8; o++) acc[o] = 0.f;
    for (int c = lane; c < CDIM; c += 32) {
        float hv = hp[c];
#pragma unroll
        for (int o = 0; o < 8; o++) acc[o] += hv * out_w[o * CDIM + c];
    }
#pragma unroll
    for (int off = 16; off; off >>= 1)
#pragma unroll
        for (int o = 0; o < 8; o++) acc[o] += __shfl_xor_sync(0xffffffffu, acc[o], off);
    if (lane == 0)
#pragma unroll
        for (int o = 0; o < 8; o++) out[(long)n * 8 + o] = acc[o] + out_b[o];
}

// ---------------- launch ----------------------------------------------------
extern "C" void kernel_launch(void* const* d_in, const int* in_sizes, int n_in,
                              void* d_out, int out_size) {
    const float* feats  = (const float*)d_in[0];
    const int*   coords = (const int*)d_in[1];
    const float* t      = (const float*)d_in[2];
    const float* in_w   = (const float*)d_in[3];
    const float* in_b   = (const float*)d_in[4];
    const float* t_w1   = (const float*)d_in[5];
    const float* t_b1   = (const float*)d_in[6];
    const float* t_w2   = (const float*)d_in[7];
    const float* t_b2   = (const float*)d_in[8];
    const float* qkv_w  = (const float*)d_in[9];
    const float* qkv_b  = (const float*)d_in[10];
    const float* proj_w = (const float*)d_in[11];
    const float* proj_b = (const float*)d_in[12];
    const float* ada_w  = (const float*)d_in[13];
    const float* ada_b  = (const float*)d_in[14];
    const float* fc1_w  = (const float*)d_in[15];
    const float* fc1_b  = (const float*)d_in[16];
    const float* fc2_w  = (const float*)d_in[17];
    const float* fc2_b  = (const float*)d_in[18];
    const float* out_w  = (const float*)d_in[19];
    const float* out_b  = (const float*)d_in[20];
    float* out = (float*)d_out;

    float *p_h, *p_hn, *p_qkv, *p_attn, *p_mlp, *p_mod, *p_siluc;
    cudaGetSymbolAddress((void**)&p_h, g_h);
    cudaGetSymbolAddress((void**)&p_hn, g_hn);
    cudaGetSymbolAddress((void**)&p_qkv, g_qkv);
    cudaGetSymbolAddress((void**)&p_attn, g_attn);
    cudaGetSymbolAddress((void**)&p_mlp, g_mlp);
    cudaGetSymbolAddress((void**)&p_mod, g_mod);
    cudaGetSymbolAddress((void**)&p_siluc, g_siluc);

    k_init<<<NTOK, 256>>>(feats, coords, in_w, in_b, p_h);
    k_tembed<<<1, 256>>>(t, t_w1, t_b1, t_w2, t_b2, p_siluc);

    for (int i = 0; i < 8; i++) {
        int shift = (i & 1) * 512;
        k_ada<<<384, 256>>>(p_siluc, ada_w + (long)i * 3072 * 512, ada_b + (long)i * 3072, p_mod);
        // attention branch
        k_modln<<<NTOK, 128>>>(p_h, p_hn, p_mod, 512, 0);
        k_gemm<0><<<dim3(12, 128), 256>>>(p_hn, qkv_w + (long)i * 1536 * 512,
                                          qkv_b + (long)i * 1536, p_qkv, nullptr, 512, 1536);
        k_attn<<<dim3(16, 8, 16), 256>>>(p_qkv, p_attn, shift);
        k_gemm<2><<<dim3(4, 128), 256>>>(p_attn, proj_w + (long)i * 512 * 512,
                                         proj_b + (long)i * 512, p_h, p_mod + 1024, 512, 512);
        // mlp branch
        k_modln<<<NTOK, 128>>>(p_h, p_hn, p_mod, 2048, 1536);
        k_gemm<1><<<dim3(16, 128), 256>>>(p_hn, fc1_w + (long)i * 2048 * 512,
                                          fc1_b + (long)i * 2048, p_mlp, nullptr, 512, 2048);
        k_gemm<2><<<dim3(4, 128), 256>>>(p_mlp, fc2_w + (long)i * 512 * 2048,
                                         fc2_b + (long)i * 512, p_h, p_mod + 2560, 2048, 512);
    }

    k_final<<<2048, 256>>>(p_h, out_w, out_b, out);
}

// round 4
// speedup vs baseline: 1.6026x; 1.6026x over previous
#include <cuda_runtime.h>
#include <cuda_bf16.h>
#include <math.h>
#include <stdint.h>

#define NTOK 16384
#define NMASK 16383
#define CDIM 512
#define CFFD 2048

// ---------------- scratch (static device globals; no allocs) ----------------
__device__ float g_h[NTOK * CDIM];
__device__ float g_hn[NTOK * CDIM];
__device__ float g_qkv[NTOK * 3 * CDIM];
__device__ float g_attn[NTOK * CDIM];
__device__ float g_mlp[NTOK * CFFD];
__device__ float g_mod[6 * CDIM];
__device__ float g_siluc[CDIM];

// ======================= HMMA helpers =======================================
#define MMA16816(acc, a, b0v, b1v)                                              \
    asm volatile(                                                               \
        "mma.sync.aligned.m16n8k16.row.col.f32.bf16.bf16.f32 "                  \
        "{%0,%1,%2,%3},{%4,%5,%6,%7},{%8,%9},{%0,%1,%2,%3};"                    \
        : "+f"((acc)[0]), "+f"((acc)[1]), "+f"((acc)[2]), "+f"((acc)[3])        \
        : "r"((a)[0]), "r"((a)[1]), "r"((a)[2]), "r"((a)[3]), "r"(b0v), "r"(b1v))

__device__ __forceinline__ void split_hi_lo(float4 v, uint2& hi, uint2& lo) {
    __nv_bfloat162 h01 = __floats2bfloat162_rn(v.x, v.y);
    __nv_bfloat162 h23 = __floats2bfloat162_rn(v.z, v.w);
    float lx = v.x - __bfloat162float(h01.x);
    float ly = v.y - __bfloat162float(h01.y);
    float lz = v.z - __bfloat162float(h23.x);
    float lw = v.w - __bfloat162float(h23.y);
    __nv_bfloat162 l01 = __floats2bfloat162_rn(lx, ly);
    __nv_bfloat162 l23 = __floats2bfloat162_rn(lz, lw);
    hi.x = *(uint32_t*)&h01; hi.y = *(uint32_t*)&h23;
    lo.x = *(uint32_t*)&l01; lo.y = *(uint32_t*)&l23;
}

// ======================= split-bf16 HMMA GEMM ===============================
// out(NxM) = A(NxK) @ W(MxK)^T, fp32 in/out, 3-term bf16 split, fp32 acc.
// CTA tile 128x128, BK=32, 8 warps (2x4), warp tile 64x32 (4x4 m16n8k16).
// smem tile layout: [row][40 bf16] (20-word pitch -> conflict-free frag LDS).
// EPI 0: out = acc + bias ; EPI 1: gelu(acc+bias) ; EPI 2: out += gate*(acc+bias)
template <int EPI>
__global__ void __launch_bounds__(256, 1)
k_mma_gemm(const float* __restrict__ A, const float* __restrict__ W,
           const float* __restrict__ bias, float* __restrict__ out,
           const float* __restrict__ gate, int K, int M) {
    extern __shared__ uint32_t smw[];  // 2 bufs x 4 tiles x 2560 words = 81920B

    const int tid = threadIdx.x;
    const int wid = tid >> 5;
    const int lane = tid & 31;
    const int g = lane >> 2;     // group row/col
    const int t = lane & 3;      // thread-in-group
    const int warp_m = wid >> 2; // 0..1
    const int warp_n = wid & 3;  // 0..3

    const int m0 = blockIdx.y * 128;
    const int n0 = blockIdx.x * 128;

    const float* Abase = A + (long)m0 * K;
    const float* Bbase = W + (long)n0 * K;
    const int NC = K >> 5;

    float acc[4][4][4];
#pragma unroll
    for (int i = 0; i < 4; i++)
#pragma unroll
        for (int j = 0; j < 4; j++)
#pragma unroll
            for (int k = 0; k < 4; k++) acc[i][j][k] = 0.f;

    float4 ra[4], rb[4];

    // ---- register-staged global load of one K-chunk (A:128x32, B:128x32) ----
    auto load_regs = [&](int c) {
        const float* Ap = Abase + c * 32;
        const float* Bp = Bbase + c * 32;
#pragma unroll
        for (int it = 0; it < 4; it++) {
            int f = it * 256 + tid;
            int r = f >> 3, q = f & 7;
            ra[it] = *(const float4*)(Ap + (long)r * K + (q << 2));
            rb[it] = *(const float4*)(Bp + (long)r * K + (q << 2));
        }
    };

    auto store_smem = [&](int b) {
        uint32_t* Ah = smw + b * 10240;
        uint32_t* Al = Ah + 2560;
        uint32_t* Bh = Al + 2560;
        uint32_t* Bl = Bh + 2560;
#pragma unroll
        for (int it = 0; it < 4; it++) {
            int f = it * 256 + tid;
            int r = f >> 3, q = f & 7;
            int wo = r * 20 + q * 2;
            uint2 hi, lo;
            split_hi_lo(ra[it], hi, lo);
            *(uint2*)(Ah + wo) = hi;
            *(uint2*)(Al + wo) = lo;
            split_hi_lo(rb[it], hi, lo);
            *(uint2*)(Bh + wo) = hi;
            *(uint2*)(Bl + wo) = lo;
        }
    };

    auto compute = [&](int b) {
        const uint32_t* Ah = smw + b * 10240;
        const uint32_t* Al = Ah + 2560;
        const uint32_t* Bh = Al + 2560;
        const uint32_t* Bl = Bh + 2560;
#pragma unroll
        for (int ks = 0; ks < 2; ks++) {
            uint32_t ah[4][4], al[4][4];
#pragma unroll
            for (int mt = 0; mt < 4; mt++) {
                int r0 = warp_m * 64 + mt * 16 + g;
                int base = r0 * 20 + ks * 8 + t;
                ah[mt][0] = Ah[base];       ah[mt][1] = Ah[base + 160];
                ah[mt][2] = Ah[base + 4];   ah[mt][3] = Ah[base + 164];
                al[mt][0] = Al[base];       al[mt][1] = Al[base + 160];
                al[mt][2] = Al[base + 4];   al[mt][3] = Al[base + 164];
            }
#pragma unroll
            for (int nt = 0; nt < 4; nt++) {
                int c0 = warp_n * 32 + nt * 8 + g;
                int bbase = c0 * 20 + ks * 8 + t;
                uint32_t bh0 = Bh[bbase], bh1 = Bh[bbase + 4];
                uint32_t bl0 = Bl[bbase], bl1 = Bl[bbase + 4];
#pragma unroll
                for (int mt = 0; mt < 4; mt++) {
                    MMA16816(acc[mt][nt], ah[mt], bh0, bh1);
                    MMA16816(acc[mt][nt], al[mt], bh0, bh1);
                    MMA16816(acc[mt][nt], ah[mt], bl0, bl1);
                }
            }
        }
    };

    load_regs(0);
    store_smem(0);
    __syncthreads();
    for (int c = 0; c < NC; c++) {
        if (c + 1 < NC) load_regs(c + 1);
        compute(c & 1);
        if (c + 1 < NC) store_smem((c + 1) & 1);
        __syncthreads();
    }

    // ---- epilogue: straight from registers, fused bias/gelu/gate ----
#pragma unroll
    for (int mt = 0; mt < 4; mt++) {
#pragma unroll
        for (int nt = 0; nt < 4; nt++) {
            float* ac = acc[mt][nt];
            int row = m0 + warp_m * 64 + mt * 16 + g;
            int col = n0 + warp_n * 32 + nt * 8 + 2 * t;
            float b0 = __ldg(bias + col), b1 = __ldg(bias + col + 1);
            float v[4];
            v[0] = ac[0] + b0; v[1] = ac[1] + b1;
            v[2] = ac[2] + b0; v[3] = ac[3] + b1;
            if (EPI == 1) {
#pragma unroll
                for (int e = 0; e < 4; e++) {
                    float x = v[e];
                    float x3 = x * x * x;
                    v[e] = 0.5f * x * (1.0f + tanhf(0.7978845608028654f * (x + 0.044715f * x3)));
                }
            }
            float* dp0 = out + (long)row * M + col;
            float* dp1 = out + (long)(row + 8) * M + col;
            if (EPI == 2) {
                float g0 = __ldg(gate + col), g1 = __ldg(gate + col + 1);
                float2 o0 = *(float2*)dp0;
                float2 o1 = *(float2*)dp1;
                o0.x += g0 * v[0]; o0.y += g1 * v[1];
                o1.x += g0 * v[2]; o1.y += g1 * v[3];
                *(float2*)dp0 = o0;
                *(float2*)dp1 = o1;
            } else {
                float2 o0 = {v[0], v[1]}, o1 = {v[2], v[3]};
                *(float2*)dp0 = o0;
                *(float2*)dp1 = o1;
            }
        }
    }
}

// ---------------- input embed: h = feats@in_w.T + in_b + pos_embed ----------
__global__ void k_init(const float* __restrict__ feats, const int* __restrict__ coords,
                       const float* __restrict__ in_w, const float* __restrict__ in_b,
                       float* __restrict__ h) {
    int n = blockIdx.x;
    int tid = threadIdx.x;  // 256
    __shared__ float f[8];
    __shared__ int cd[3];
    if (tid < 8) f[tid] = feats[n * 8 + tid];
    if (tid < 3) cd[tid] = coords[n * 3 + tid];
    __syncthreads();
    for (int c = tid; c < CDIM; c += 256) {
        float acc = in_b[c];
#pragma unroll
        for (int i = 0; i < 8; i++) acc += f[i] * in_w[c * 8 + i];
        if (c < 510) {
            int j = c / 170;
            int k = c - j * 170;
            int kk = (k < 85) ? k : k - 85;
            float freq = expf((float)kk * (-9.210340371976184f / 85.0f));
            float o = (float)cd[j] * freq;
            acc += (k < 85) ? sinf(o) : cosf(o);
        }
        h[(long)n * CDIM + c] = acc;
    }
}

// ---------------- t embedding -> silu(c) ------------------------------------
__global__ void k_tembed(const float* __restrict__ t,
                         const float* __restrict__ w1, const float* __restrict__ b1,
                         const float* __restrict__ w2, const float* __restrict__ b2,
                         float* __restrict__ siluc) {
    __shared__ float emb[256];
    __shared__ float hid[512];
    int tid = threadIdx.x;  // 256
    float tv = t[0];
    if (tid < 128) {
        float fr = expf((float)tid * (-9.210340371976184f / 128.0f));
        float a = tv * fr;
        emb[tid] = cosf(a);
        emb[128 + tid] = sinf(a);
    }
    __syncthreads();
    for (int c = tid; c < 512; c += 256) {
        float acc = b1[c];
        const float* wr = w1 + (long)c * 256;
        for (int k = 0; k < 256; k++) acc += emb[k] * wr[k];
        hid[c] = acc / (1.0f + expf(-acc));
    }
    __syncthreads();
    for (int c = tid; c < 512; c += 256) {
        float acc = b2[c];
        const float* wr = w2 + (long)c * 512;
        for (int k = 0; k < 512; k++) acc += hid[k] * wr[k];
        siluc[c] = acc / (1.0f + expf(-acc));
    }
}

// ---------------- adaLN modulation ------------------------------------------
__global__ void k_ada(const float* __restrict__ siluc, const float* __restrict__ ada_w,
                      const float* __restrict__ ada_b, float* __restrict__ mod) {
    __shared__ float sc[512];
    int tid = threadIdx.x;  // 256
    for (int c = tid; c < 512; c += 256) sc[c] = siluc[c];
    __syncthreads();
    int warp = tid >> 5, lane = tid & 31;
    int m = blockIdx.x * 8 + warp;
    const float* wr = ada_w + (long)m * 512;
    float acc = 0.f;
    for (int k = lane; k < 512; k += 32) acc += sc[k] * wr[k];
#pragma unroll
    for (int off = 16; off; off >>= 1) acc += __shfl_xor_sync(0xffffffffu, acc, off);
    if (lane == 0) mod[m] = acc + ada_b[m];
}

// ---------------- LN + modulation -------------------------------------------
__global__ void k_modln(const float* __restrict__ h, float* __restrict__ hn,
                        const float* __restrict__ mod, int sc_off, int sm_off) {
    int n = blockIdx.x;
    int tid = threadIdx.x;  // 128
    const float4* hp = (const float4*)(h + (long)n * CDIM);
    float4 x = hp[tid];
    float s = x.x + x.y + x.z + x.w;
    float sq = x.x * x.x + x.y * x.y + x.z * x.z + x.w * x.w;
#pragma unroll
    for (int off = 16; off; off >>= 1) {
        s += __shfl_xor_sync(0xffffffffu, s, off);
        sq += __shfl_xor_sync(0xffffffffu, sq, off);
    }
    __shared__ float rs[4], rq[4];
    int warp = tid >> 5;
    if ((tid & 31) == 0) { rs[warp] = s; rq[warp] = sq; }
    __syncthreads();
    float S = rs[0] + rs[1] + rs[2] + rs[3];
    float SQ = rq[0] + rq[1] + rq[2] + rq[3];
    float mean = S * (1.0f / 512.0f);
    float var = SQ * (1.0f / 512.0f) - mean * mean;
    float inv = rsqrtf(var + 1e-6f);
    int c = tid * 4;
    float4 scv = *(const float4*)(mod + sc_off + c);
    float4 smv = *(const float4*)(mod + sm_off + c);
    float4 o;
    o.x = (x.x - mean) * inv * (1.0f + scv.x) + smv.x;
    o.y = (x.y - mean) * inv * (1.0f + scv.y) + smv.y;
    o.z = (x.z - mean) * inv * (1.0f + scv.z) + smv.z;
    o.w = (x.w - mean) * inv * (1.0f + scv.w) + smv.w;
    ((float4*)(hn + (long)n * CDIM))[tid] = o;
}

// ---------------- windowed flash attention (fp32 SIMT) ----------------------
__global__ void __launch_bounds__(256)
k_attn(const float* __restrict__ qkv, float* __restrict__ attn, int shift) {
    __shared__ float Qt[64][68];
    __shared__ float Kt[64][36];
    __shared__ float Vs[32][64];
    __shared__ float Pt[32][68];
    __shared__ float red[64][17];
    __shared__ float m_s[64], l_s[64], alpha_s[64];

    int tid = threadIdx.x;
    int tx = tid & 15, ty = tid >> 4;
    int qt = blockIdx.x, hh = blockIdx.y, w = blockIdx.z;
    int qbase = w * 1024 + qt * 64;

    {
        int i = tid >> 2;
        int tok = (qbase + i + shift) & NMASK;
        const float* qp = qkv + (long)tok * 1536 + (hh << 6);
        int q0 = (tid & 3) * 4;
#pragma unroll
        for (int rep = 0; rep < 4; rep++) {
            int d0 = q0 + rep * 16;
            float4 v = *(const float4*)(qp + d0);
            Qt[d0 + 0][i] = 0.125f * v.x;
            Qt[d0 + 1][i] = 0.125f * v.y;
            Qt[d0 + 2][i] = 0.125f * v.z;
            Qt[d0 + 3][i] = 0.125f * v.w;
        }
    }
    if (tid < 64) { m_s[tid] = -1e30f; l_s[tid] = 0.f; }

    float o[4][4];
#pragma unroll
    for (int i = 0; i < 4; i++)
#pragma unroll
        for (int j = 0; j < 4; j++) o[i][j] = 0.f;

    for (int j0 = 0; j0 < 1024; j0 += 32) {
        int jr = tid >> 3;
        int tok = (w * 1024 + j0 + jr + shift) & NMASK;
        const float* kp = qkv + (long)tok * 1536 + 512 + (hh << 6);
        const float* vp = kp + 512;
        int d0 = (tid & 7) * 4;
        float4 ka = *(const float4*)(kp + d0);
        float4 kb = *(const float4*)(kp + d0 + 32);
        float4 va = *(const float4*)(vp + d0);
        float4 vb = *(const float4*)(vp + d0 + 32);

        __syncthreads();
        Kt[d0 + 0][jr] = ka.x; Kt[d0 + 1][jr] = ka.y;
        Kt[d0 + 2][jr] = ka.z; Kt[d0 + 3][jr] = ka.w;
        Kt[d0 + 32][jr] = kb.x; Kt[d0 + 33][jr] = kb.y;
        Kt[d0 + 34][jr] = kb.z; Kt[d0 + 35][jr] = kb.w;
        *(float4*)&Vs[jr][d0] = va;
        *(float4*)&Vs[jr][d0 + 32] = vb;
        __syncthreads();

        float s0[4][2];
#pragma unroll
        for (int i = 0; i < 4; i++) { s0[i][0] = 0.f; s0[i][1] = 0.f; }
#pragma unroll
        for (int d = 0; d < 64; d++) {
            float4 qv = *(const float4*)&Qt[d][4 * ty];
            float k0v = Kt[d][2 * tx], k1v = Kt[d][2 * tx + 1];
            s0[0][0] += qv.x * k0v; s0[0][1] += qv.x * k1v;
            s0[1][0] += qv.y * k0v; s0[1][1] += qv.y * k1v;
            s0[2][0] += qv.z * k0v; s0[2][1] += qv.z * k1v;
            s0[3][0] += qv.w * k0v; s0[3][1] += qv.w * k1v;
        }

#pragma unroll
        for (int ii = 0; ii < 4; ii++)
            red[4 * ty + ii][tx] = fmaxf(s0[ii][0], s0[ii][1]);
        __syncthreads();
        if (tid < 64) {
            float mx = red[tid][0];
#pragma unroll
            for (int x = 1; x < 16; x++) mx = fmaxf(mx, red[tid][x]);
            float mo = m_s[tid];
            float mn = fmaxf(mo, mx);
            m_s[tid] = mn;
            alpha_s[tid] = __expf(mo - mn);
        }
        __syncthreads();

#pragma unroll
        for (int ii = 0; ii < 4; ii++) {
            int r = 4 * ty + ii;
            float mn = m_s[r];
            float a = alpha_s[r];
            float p0 = __expf(s0[ii][0] - mn);
            float p1 = __expf(s0[ii][1] - mn);
            o[ii][0] *= a; o[ii][1] *= a; o[ii][2] *= a; o[ii][3] *= a;
            Pt[2 * tx + 0][r] = p0;
            Pt[2 * tx + 1][r] = p1;
            red[r][tx] = p0 + p1;
        }
        __syncthreads();
        if (tid < 64) {
            float sm = 0.f;
#pragma unroll
            for (int x = 0; x < 16; x++) sm += red[tid][x];
            l_s[tid] = l_s[tid] * alpha_s[tid] + sm;
        }

#pragma unroll 8
        for (int j = 0; j < 32; j++) {
            float4 pv = *(const float4*)&Pt[j][4 * ty];
            float4 vv = *(const float4*)&Vs[j][4 * tx];
            o[0][0] += pv.x * vv.x; o[0][1] += pv.x * vv.y; o[0][2] += pv.x * vv.z; o[0][3] += pv.x * vv.w;
            o[1][0] += pv.y * vv.x; o[1][1] += pv.y * vv.y; o[1][2] += pv.y * vv.z; o[1][3] += pv.y * vv.w;
            o[2][0] += pv.z * vv.x; o[2][1] += pv.z * vv.y; o[2][2] += pv.z * vv.z; o[2][3] += pv.z * vv.w;
            o[3][0] += pv.w * vv.x; o[3][1] += pv.w * vv.y; o[3][2] += pv.w * vv.z; o[3][3] += pv.w * vv.w;
        }
    }
    __syncthreads();

#pragma unroll
    for (int ii = 0; ii < 4; ii++) {
        int r = 4 * ty + ii;
        float inv = 1.0f / l_s[r];
        int tok = (qbase + r + shift) & NMASK;
        float4 res;
        res.x = o[ii][0] * inv; res.y = o[ii][1] * inv;
        res.z = o[ii][2] * inv; res.w = o[ii][3] * inv;
        *(float4*)(attn + (long)tok * CDIM + (hh << 6) + 4 * tx) = res;
    }
}

// ---------------- output head -----------------------------------------------
__global__ void k_final(const float* __restrict__ h, const float* __restrict__ out_w,
                        const float* __restrict__ out_b, float* __restrict__ out) {
    int warp = threadIdx.x >> 5, lane = threadIdx.x & 31;
    int n = blockIdx.x * 8 + warp;
    const float* hp = h + (long)n * CDIM;
    float acc[8];
#pragma unroll
    for (int o = 0; o < 8; o++) acc[o] = 0.f;
    for (int c = lane; c < CDIM; c += 32) {
        float hv = hp[c];
#pragma unroll
        for (int o = 0; o < 8; o++) acc[o] += hv * out_w[o * CDIM + c];
    }
#pragma unroll
    for (int off = 16; off; off >>= 1)
#pragma unroll
        for (int o = 0; o < 8; o++) acc[o] += __shfl_xor_sync(0xffffffffu, acc[o], off);
    if (lane == 0)
#pragma unroll
        for (int o = 0; o < 8; o++) out[(long)n * 8 + o] = acc[o] + out_b[o];
}

// ---------------- launch ----------------------------------------------------
extern "C" void kernel_launch(void* const* d_in, const int* in_sizes, int n_in,
                              void* d_out, int out_size) {
    const float* feats  = (const float*)d_in[0];
    const int*   coords = (const int*)d_in[1];
    const float* t      = (const float*)d_in[2];
    const float* in_w   = (const float*)d_in[3];
    const float* in_b   = (const float*)d_in[4];
    const float* t_w1   = (const float*)d_in[5];
    const float* t_b1   = (const float*)d_in[6];
    const float* t_w2   = (const float*)d_in[7];
    const float* t_b2   = (const float*)d_in[8];
    const float* qkv_w  = (const float*)d_in[9];
    const float* qkv_b  = (const float*)d_in[10];
    const float* proj_w = (const float*)d_in[11];
    const float* proj_b = (const float*)d_in[12];
    const float* ada_w  = (const float*)d_in[13];
    const float* ada_b  = (const float*)d_in[14];
    const float* fc1_w  = (const float*)d_in[15];
    const float* fc1_b  = (const float*)d_in[16];
    const float* fc2_w  = (const float*)d_in[17];
    const float* fc2_b  = (const float*)d_in[18];
    const float* out_w  = (const float*)d_in[19];
    const float* out_b  = (const float*)d_in[20];
    float* out = (float*)d_out;

    float *p_h, *p_hn, *p_qkv, *p_attn, *p_mlp, *p_mod, *p_siluc;
    cudaGetSymbolAddress((void**)&p_h, g_h);
    cudaGetSymbolAddress((void**)&p_hn, g_hn);
    cudaGetSymbolAddress((void**)&p_qkv, g_qkv);
    cudaGetSymbolAddress((void**)&p_attn, g_attn);
    cudaGetSymbolAddress((void**)&p_mlp, g_mlp);
    cudaGetSymbolAddress((void**)&p_mod, g_mod);
    cudaGetSymbolAddress((void**)&p_siluc, g_siluc);

    const int GSM = 81920;  // 2 bufs x (Ah,Al,Bh,Bl) x 10240B
    cudaFuncSetAttribute(k_mma_gemm<0>, cudaFuncAttributeMaxDynamicSharedMemorySize, GSM);
    cudaFuncSetAttribute(k_mma_gemm<1>, cudaFuncAttributeMaxDynamicSharedMemorySize, GSM);
    cudaFuncSetAttribute(k_mma_gemm<2>, cudaFuncAttributeMaxDynamicSharedMemorySize, GSM);

    k_init<<<NTOK, 256>>>(feats, coords, in_w, in_b, p_h);
    k_tembed<<<1, 256>>>(t, t_w1, t_b1, t_w2, t_b2, p_siluc);

    for (int i = 0; i < 8; i++) {
        int shift = (i & 1) * 512;
        k_ada<<<384, 256>>>(p_siluc, ada_w + (long)i * 3072 * 512, ada_b + (long)i * 3072, p_mod);
        // attention branch
        k_modln<<<NTOK, 128>>>(p_h, p_hn, p_mod, 512, 0);
        k_mma_gemm<0><<<dim3(12, 128), 256, GSM>>>(
            p_hn, qkv_w + (long)i * 1536 * 512, qkv_b + (long)i * 1536, p_qkv, nullptr, 512, 1536);
        k_attn<<<dim3(16, 8, 16), 256>>>(p_qkv, p_attn, shift);
        k_mma_gemm<2><<<dim3(4, 128), 256, GSM>>>(
            p_attn, proj_w + (long)i * 512 * 512, proj_b + (long)i * 512, p_h, p_mod + 1024, 512, 512);
        // mlp branch
        k_modln<<<NTOK, 128>>>(p_h, p_hn, p_mod, 2048, 1536);
        k_mma_gemm<1><<<dim3(16, 128), 256, GSM>>>(
            p_hn, fc1_w + (long)i * 2048 * 512, fc1_b + (long)i * 2048, p_mlp, nullptr, 512, 2048);
        k_mma_gemm<2><<<dim3(4, 128), 256, GSM>>>(
            p_mlp, fc2_w + (long)i * 512 * 2048, fc2_b + (long)i * 512, p_h, p_mod + 2560, 2048, 512);
    }

    k_final<<<2048, 256>>>(p_h, out_w, out_b, out);
}

// round 6
// speedup vs baseline: 2.2454x; 1.4010x over previous
#include <cuda_runtime.h>
#include <cuda_bf16.h>
#include <math.h>
#include <stdint.h>

#define NTOK 16384
#define NMASK 16383
#define CDIM 512
#define CFFD 2048

typedef __nv_bfloat16 bf16;

// ---------------- scratch (static device globals; no allocs) ----------------
__device__ float g_h[NTOK * CDIM];
__device__ float g_mod[6 * CDIM];
__device__ float g_siluc[CDIM];
__device__ bf16 g_hn_h[NTOK * CDIM], g_hn_l[NTOK * CDIM];
__device__ bf16 g_qkv_h[NTOK * 3 * CDIM], g_qkv_l[NTOK * 3 * CDIM];
__device__ bf16 g_attn_h[NTOK * CDIM], g_attn_l[NTOK * CDIM];
__device__ bf16 g_mlp_h[NTOK * CFFD], g_mlp_l[NTOK * CFFD];
// weights hi/lo: [qkv | proj | fc1 | fc2]
#define OFF_QKV 0
#define OFF_PROJ 6291456
#define OFF_FC1 8388608
#define OFF_FC2 16777216
__device__ bf16 g_wh[25165824], g_wl[25165824];

// ======================= helpers ============================================
#define MMA16816(acc, a, b0v, b1v)                                              \
    asm volatile(                                                               \
        "mma.sync.aligned.m16n8k16.row.col.f32.bf16.bf16.f32 "                  \
        "{%0,%1,%2,%3},{%4,%5,%6,%7},{%8,%9},{%0,%1,%2,%3};"                    \
        : "+f"((acc)[0]), "+f"((acc)[1]), "+f"((acc)[2]), "+f"((acc)[3])        \
        : "r"((a)[0]), "r"((a)[1]), "r"((a)[2]), "r"((a)[3]), "r"(b0v), "r"(b1v))

__device__ __forceinline__ uint32_t pack_split(float a, float b, uint32_t& lo) {
    __nv_bfloat162 h = __floats2bfloat162_rn(a, b);
    float ra = a - __bfloat162float(h.x);
    float rb = b - __bfloat162float(h.y);
    __nv_bfloat162 l = __floats2bfloat162_rn(ra, rb);
    lo = *(uint32_t*)&l;
    return *(uint32_t*)&h;
}

// weight / activation pre-split: fp32 -> bf16 hi + bf16 lo
__global__ void k_split(const float* __restrict__ src, bf16* __restrict__ dh,
                        bf16* __restrict__ dl, int n4) {
    int i = blockIdx.x * 256 + threadIdx.x;
    if (i >= n4) return;
    float4 v = ((const float4*)src)[i];
    uint2 hv, lv;
    hv.x = pack_split(v.x, v.y, lv.x);
    hv.y = pack_split(v.z, v.w, lv.y);
    ((uint2*)dh)[i] = hv;
    ((uint2*)dl)[i] = lv;
}

// ======================= split-bf16 HMMA GEMM ===============================
// out(NxM) = A(NxK) @ W(MxK)^T; A,W given pre-split (hi/lo bf16); fp32 acc.
// CTA 128x128, BK=32, 8 warps (2x4), warp tile 64x32.
// EPI 0: split-write (qkv; scale 0.125 on cols<512)
// EPI 1: gelu then split-write
// EPI 2: outf += gate[col]*(acc+bias)   (fp32 RMW)
template <int EPI>
__global__ void __launch_bounds__(256, 1)
k_mma_gemm(const bf16* __restrict__ Ah, const bf16* __restrict__ Al,
           const bf16* __restrict__ Wh, const bf16* __restrict__ Wl,
           const float* __restrict__ bias, float* __restrict__ outf,
           bf16* __restrict__ oh, bf16* __restrict__ ol,
           const float* __restrict__ gate, int K, int M) {
    extern __shared__ uint32_t smw[];  // 2 bufs x 4 tiles x 2560 words = 81920B

    const int tid = threadIdx.x;
    const int wid = tid >> 5;
    const int lane = tid & 31;
    const int g = lane >> 2;
    const int t = lane & 3;
    const int warp_m = wid >> 2;
    const int warp_n = wid & 3;

    const int m0 = blockIdx.y * 128;
    const int n0 = blockIdx.x * 128;

    const bf16* Ah_p = Ah + (long)m0 * K;
    const bf16* Al_p = Al + (long)m0 * K;
    const bf16* Bh_p = Wh + (long)n0 * K;
    const bf16* Bl_p = Wl + (long)n0 * K;
    const int NC = K >> 5;

    float acc[4][4][4];
#pragma unroll
    for (int i = 0; i < 4; i++)
#pragma unroll
        for (int j = 0; j < 4; j++)
#pragma unroll
            for (int k = 0; k < 4; k++) acc[i][j][k] = 0.f;

    uint4 rah[2], ral[2], rbh[2], rbl[2];

    auto load_regs = [&](int c) {
#pragma unroll
        for (int it = 0; it < 2; it++) {
            int f = it * 256 + tid;
            int r = f >> 2, q = f & 3;
            long off = (long)r * K + c * 32 + q * 8;
            rah[it] = *(const uint4*)(Ah_p + off);
            ral[it] = *(const uint4*)(Al_p + off);
            rbh[it] = *(const uint4*)(Bh_p + off);
            rbl[it] = *(const uint4*)(Bl_p + off);
        }
    };

    auto store_smem = [&](int b) {
        uint32_t* sAh = smw + b * 10240;
        uint32_t* sAl = sAh + 2560;
        uint32_t* sBh = sAl + 2560;
        uint32_t* sBl = sBh + 2560;
#pragma unroll
        for (int it = 0; it < 2; it++) {
            int f = it * 256 + tid;
            int r = f >> 2, q = f & 3;
            int wo = r * 20 + q * 4;
            *(uint4*)&sAh[wo] = rah[it];
            *(uint4*)&sAl[wo] = ral[it];
            *(uint4*)&sBh[wo] = rbh[it];
            *(uint4*)&sBl[wo] = rbl[it];
        }
    };

    auto compute = [&](int b) {
        const uint32_t* sAh = smw + b * 10240;
        const uint32_t* sAl = sAh + 2560;
        const uint32_t* sBh = sAl + 2560;
        const uint32_t* sBl = sBh + 2560;
#pragma unroll
        for (int ks = 0; ks < 2; ks++) {
            uint32_t ah[4][4], al[4][4];
#pragma unroll
            for (int mt = 0; mt < 4; mt++) {
                int base = (warp_m * 64 + mt * 16 + g) * 20 + ks * 8 + t;
                ah[mt][0] = sAh[base];     ah[mt][1] = sAh[base + 160];
                ah[mt][2] = sAh[base + 4]; ah[mt][3] = sAh[base + 164];
                al[mt][0] = sAl[base];     al[mt][1] = sAl[base + 160];
                al[mt][2] = sAl[base + 4]; al[mt][3] = sAl[base + 164];
            }
#pragma unroll
            for (int nt = 0; nt < 4; nt++) {
                int bb = (warp_n * 32 + nt * 8 + g) * 20 + ks * 8 + t;
                uint32_t bh0 = sBh[bb], bh1 = sBh[bb + 4];
                uint32_t bl0 = sBl[bb], bl1 = sBl[bb + 4];
#pragma unroll
                for (int mt = 0; mt < 4; mt++) {
                    MMA16816(acc[mt][nt], ah[mt], bh0, bh1);
                    MMA16816(acc[mt][nt], al[mt], bh0, bh1);
                    MMA16816(acc[mt][nt], ah[mt], bl0, bl1);
                }
            }
        }
    };

    load_regs(0);
    store_smem(0);
    __syncthreads();
    for (int c = 0; c < NC; c++) {
        if (c + 1 < NC) load_regs(c + 1);
        compute(c & 1);
        if (c + 1 < NC) store_smem((c + 1) & 1);
        __syncthreads();
    }

    // ---- epilogue ----
#pragma unroll
    for (int mt = 0; mt < 4; mt++) {
#pragma unroll
        for (int nt = 0; nt < 4; nt++) {
            float* ac = acc[mt][nt];
            int row = m0 + warp_m * 64 + mt * 16 + g;
            int col = n0 + warp_n * 32 + nt * 8 + 2 * t;
            float b0 = __ldg(bias + col), b1 = __ldg(bias + col + 1);
            float v[4];
            v[0] = ac[0] + b0; v[1] = ac[1] + b1;
            v[2] = ac[2] + b0; v[3] = ac[3] + b1;
            if (EPI == 0) {
                if (col < 512) {
#pragma unroll
                    for (int e = 0; e < 4; e++) v[e] *= 0.125f;
                }
            }
            if (EPI == 1) {
#pragma unroll
                for (int e = 0; e < 4; e++) {
                    float x = v[e];
                    float x3 = x * x * x;
                    v[e] = 0.5f * x * (1.0f + tanhf(0.7978845608028654f * (x + 0.044715f * x3)));
                }
            }
            if (EPI == 2) {
                float* dp0 = outf + (long)row * M + col;
                float* dp1 = outf + (long)(row + 8) * M + col;
                float g0 = __ldg(gate + col), g1 = __ldg(gate + col + 1);
                float2 o0 = *(float2*)dp0;
                float2 o1 = *(float2*)dp1;
                o0.x += g0 * v[0]; o0.y += g1 * v[1];
                o1.x += g0 * v[2]; o1.y += g1 * v[3];
                *(float2*)dp0 = o0;
                *(float2*)dp1 = o1;
            } else {
                uint32_t lo0, lo1;
                uint32_t hi0 = pack_split(v[0], v[1], lo0);
                uint32_t hi1 = pack_split(v[2], v[3], lo1);
                *(uint32_t*)(oh + (long)row * M + col) = hi0;
                *(uint32_t*)(ol + (long)row * M + col) = lo0;
                *(uint32_t*)(oh + (long)(row + 8) * M + col) = hi1;
                *(uint32_t*)(ol + (long)(row + 8) * M + col) = lo1;
            }
        }
    }
}

// ======================= HMMA windowed flash attention ======================
// grid (qtile=8, head=8, window=16), 256 thr (8 warps), BQ=128, BKV=64, D=64.
// q pre-scaled by 0.125 at the qkv epilogue. 3-term split on QK and PV.
__global__ void __launch_bounds__(256, 1)
k_attn_mma(const bf16* __restrict__ qh, const bf16* __restrict__ ql,
           bf16* __restrict__ oh, bf16* __restrict__ ol, int shift) {
    extern __shared__ uint32_t sw[];
    uint32_t* Qh = sw;            // 128 rows x 36 words (72 bf16 pitch)
    uint32_t* Ql = Qh + 4608;
    uint32_t* Kh = Ql + 4608;     // 64 rows x 36 words
    uint32_t* Kl = Kh + 2304;
    uint32_t* Vh = Kl + 2304;     // 64 d-rows x 36 words (token-pair packed)
    uint32_t* Vl = Vh + 2304;

    const int tid = threadIdx.x;
    const int wid = tid >> 5;
    const int lane = tid & 31;
    const int g = lane >> 2;
    const int t = lane & 3;

    const int qt = blockIdx.x, hh = blockIdx.y, w = blockIdx.z;
    const int qbase = w * 1024 + qt * 128;
    const int r0 = wid * 16;

    // ---- load Q tile (rows 0..127) ----
    {
        int row = tid >> 1, hf = tid & 1;
        int tok = (qbase + row + shift) & NMASK;
        const uint4* ph = (const uint4*)(qh + (long)tok * 1536 + hh * 64 + hf * 32);
        const uint4* pl = (const uint4*)(ql + (long)tok * 1536 + hh * 64 + hf * 32);
        int wo = row * 36 + hf * 16;
#pragma unroll
        for (int q = 0; q < 4; q++) {
            *(uint4*)&Qh[wo + q * 4] = ph[q];
            *(uint4*)&Ql[wo + q * 4] = pl[q];
        }
    }

    float accO[8][4];
#pragma unroll
    for (int i = 0; i < 8; i++)
#pragma unroll
        for (int j = 0; j < 4; j++) accO[i][j] = 0.f;
    float m0 = -1e30f, m1 = -1e30f, l0 = 0.f, l1 = 0.f;

    for (int c = 0; c < 16; c++) {
        int j0 = c * 64;
        __syncthreads();
        // K chunk: rows 0..63, straight copy
        {
            int jr = tid >> 2, qf = tid & 3;
            int tok = (w * 1024 + j0 + jr + shift) & NMASK;
            const uint4* ph = (const uint4*)(qh + (long)tok * 1536 + 512 + hh * 64 + qf * 16);
            const uint4* pl = (const uint4*)(ql + (long)tok * 1536 + 512 + hh * 64 + qf * 16);
            int wo = jr * 36 + qf * 8;
            *(uint4*)&Kh[wo] = ph[0];
            *(uint4*)&Kh[wo + 4] = ph[1];
            *(uint4*)&Kl[wo] = pl[0];
            *(uint4*)&Kl[wo + 4] = pl[1];
        }
        // V chunk: transpose-pack Vt[d][token-pair]
        {
            int jp = tid & 31, dg = tid >> 5;
            int t0 = (w * 1024 + j0 + 2 * jp + shift) & NMASK;
            int t1 = (w * 1024 + j0 + 2 * jp + 1 + shift) & NMASK;
            long o0 = (long)t0 * 1536 + 1024 + hh * 64 + dg * 8;
            long o1 = (long)t1 * 1536 + 1024 + hh * 64 + dg * 8;
            uint4 vh0 = *(const uint4*)(qh + o0);
            uint4 vh1 = *(const uint4*)(qh + o1);
            uint4 vl0 = *(const uint4*)(ql + o0);
            uint4 vl1 = *(const uint4*)(ql + o1);
            const bf16* a0 = (const bf16*)&vh0;
            const bf16* a1 = (const bf16*)&vh1;
            const bf16* b0 = (const bf16*)&vl0;
            const bf16* b1 = (const bf16*)&vl1;
#pragma unroll
            for (int i = 0; i < 8; i++) {
                uint32_t pv, qv;
                ((bf16*)&pv)[0] = a0[i]; ((bf16*)&pv)[1] = a1[i];
                ((bf16*)&qv)[0] = b0[i]; ((bf16*)&qv)[1] = b1[i];
                Vh[(dg * 8 + i) * 36 + jp] = pv;
                Vl[(dg * 8 + i) * 36 + jp] = qv;
            }
        }
        __syncthreads();

        // ---- S = Q K^T (16x64 per warp), 3-term split ----
        float accS[8][4];
#pragma unroll
        for (int i = 0; i < 8; i++)
#pragma unroll
            for (int j = 0; j < 4; j++) accS[i][j] = 0.f;
#pragma unroll
        for (int ks = 0; ks < 4; ks++) {
            uint32_t ah[4], al[4];
            int base = (r0 + g) * 36 + ks * 8 + t;
            int base8 = (r0 + g + 8) * 36 + ks * 8 + t;
            ah[0] = Qh[base]; ah[1] = Qh[base8]; ah[2] = Qh[base + 4]; ah[3] = Qh[base8 + 4];
            al[0] = Ql[base]; al[1] = Ql[base8]; al[2] = Ql[base + 4]; al[3] = Ql[base8 + 4];
#pragma unroll
            for (int nt = 0; nt < 8; nt++) {
                int bb = (nt * 8 + g) * 36 + ks * 8 + t;
                uint32_t bh0 = Kh[bb], bh1 = Kh[bb + 4];
                uint32_t bl0 = Kl[bb], bl1 = Kl[bb + 4];
                MMA16816(accS[nt], ah, bh0, bh1);
                MMA16816(accS[nt], al, bh0, bh1);
                MMA16816(accS[nt], ah, bl0, bl1);
            }
        }

        // ---- online softmax ----
        float ml0 = -1e30f, ml1 = -1e30f;
#pragma unroll
        for (int nt = 0; nt < 8; nt++) {
            ml0 = fmaxf(ml0, fmaxf(accS[nt][0], accS[nt][1]));
            ml1 = fmaxf(ml1, fmaxf(accS[nt][2], accS[nt][3]));
        }
#pragma unroll
        for (int off = 1; off < 4; off <<= 1) {
            ml0 = fmaxf(ml0, __shfl_xor_sync(0xffffffffu, ml0, off));
            ml1 = fmaxf(ml1, __shfl_xor_sync(0xffffffffu, ml1, off));
        }
        float mn0 = fmaxf(m0, ml0), mn1 = fmaxf(m1, ml1);
        float alpha0 = __expf(m0 - mn0), alpha1 = __expf(m1 - mn1);
        m0 = mn0; m1 = mn1;
        float rs0 = 0.f, rs1 = 0.f;
#pragma unroll
        for (int nt = 0; nt < 8; nt++) {
            accS[nt][0] = __expf(accS[nt][0] - mn0);
            accS[nt][1] = __expf(accS[nt][1] - mn0);
            accS[nt][2] = __expf(accS[nt][2] - mn1);
            accS[nt][3] = __expf(accS[nt][3] - mn1);
            rs0 += accS[nt][0] + accS[nt][1];
            rs1 += accS[nt][2] + accS[nt][3];
        }
#pragma unroll
        for (int off = 1; off < 4; off <<= 1) {
            rs0 += __shfl_xor_sync(0xffffffffu, rs0, off);
            rs1 += __shfl_xor_sync(0xffffffffu, rs1, off);
        }
        l0 = l0 * alpha0 + rs0;
        l1 = l1 * alpha1 + rs1;
#pragma unroll
        for (int nt = 0; nt < 8; nt++) {
            accO[nt][0] *= alpha0; accO[nt][1] *= alpha0;
            accO[nt][2] *= alpha1; accO[nt][3] *= alpha1;
        }

        // ---- O += P V (P split in registers) ----
#pragma unroll
        for (int kt = 0; kt < 4; kt++) {
            uint32_t ph[4], pl[4];
            ph[0] = pack_split(accS[2 * kt][0], accS[2 * kt][1], pl[0]);
            ph[1] = pack_split(accS[2 * kt][2], accS[2 * kt][3], pl[1]);
            ph[2] = pack_split(accS[2 * kt + 1][0], accS[2 * kt + 1][1], pl[2]);
            ph[3] = pack_split(accS[2 * kt + 1][2], accS[2 * kt + 1][3], pl[3]);
#pragma unroll
            for (int nt = 0; nt < 8; nt++) {
                int vb = (nt * 8 + g) * 36 + kt * 8 + t;
                uint32_t vh0 = Vh[vb], vh1 = Vh[vb + 4];
                uint32_t vl0 = Vl[vb], vl1 = Vl[vb + 4];
                MMA16816(accO[nt], ph, vh0, vh1);
                MMA16816(accO[nt], pl, vh0, vh1);
                MMA16816(accO[nt], ph, vl0, vl1);
            }
        }
    }

    // ---- finalize + split write ----
    float inv0 = 1.0f / l0, inv1 = 1.0f / l1;
    int tokA = (qbase + r0 + g + shift) & NMASK;
    int tokB = (qbase + r0 + g + 8 + shift) & NMASK;
#pragma unroll
    for (int nt = 0; nt < 8; nt++) {
        int col = hh * 64 + nt * 8 + 2 * t;
        uint32_t loA, loB;
        uint32_t hiA = pack_split(accO[nt][0] * inv0, accO[nt][1] * inv0, loA);
        uint32_t hiB = pack_split(accO[nt][2] * inv1, accO[nt][3] * inv1, loB);
        *(uint32_t*)(oh + (long)tokA * CDIM + col) = hiA;
        *(uint32_t*)(ol + (long)tokA * CDIM + col) = loA;
        *(uint32_t*)(oh + (long)tokB * CDIM + col) = hiB;
        *(uint32_t*)(ol + (long)tokB * CDIM + col) = loB;
    }
}

// ---------------- input embed ------------------------------------------------
__global__ void k_init(const float* __restrict__ feats, const int* __restrict__ coords,
                       const float* __restrict__ in_w, const float* __restrict__ in_b,
                       float* __restrict__ h) {
    int n = blockIdx.x;
    int tid = threadIdx.x;  // 256
    __shared__ float f[8];
    __shared__ int cd[3];
    if (tid < 8) f[tid] = feats[n * 8 + tid];
    if (tid < 3) cd[tid] = coords[n * 3 + tid];
    __syncthreads();
    for (int c = tid; c < CDIM; c += 256) {
        float acc = in_b[c];
#pragma unroll
        for (int i = 0; i < 8; i++) acc += f[i] * in_w[c * 8 + i];
        if (c < 510) {
            int j = c / 170;
            int k = c - j * 170;
            int kk = (k < 85) ? k : k - 85;
            float freq = expf((float)kk * (-9.210340371976184f / 85.0f));
            float o = (float)cd[j] * freq;
            acc += (k < 85) ? sinf(o) : cosf(o);
        }
        h[(long)n * CDIM + c] = acc;
    }
}

// ---------------- t embedding -> silu(c) ------------------------------------
__global__ void k_tembed(const float* __restrict__ t,
                         const float* __restrict__ w1, const float* __restrict__ b1,
                         const float* __restrict__ w2, const float* __restrict__ b2,
                         float* __restrict__ siluc) {
    __shared__ float emb[256];
    __shared__ float hid[512];
    int tid = threadIdx.x;  // 256
    float tv = t[0];
    if (tid < 128) {
        float fr = expf((float)tid * (-9.210340371976184f / 128.0f));
        float a = tv * fr;
        emb[tid] = cosf(a);
        emb[128 + tid] = sinf(a);
    }
    __syncthreads();
    for (int c = tid; c < 512; c += 256) {
        float acc = b1[c];
        const float* wr = w1 + (long)c * 256;
        for (int k = 0; k < 256; k++) acc += emb[k] * wr[k];
        hid[c] = acc / (1.0f + expf(-acc));
    }
    __syncthreads();
    for (int c = tid; c < 512; c += 256) {
        float acc = b2[c];
        const float* wr = w2 + (long)c * 512;
        for (int k = 0; k < 512; k++) acc += hid[k] * wr[k];
        siluc[c] = acc / (1.0f + expf(-acc));
    }
}

// ---------------- adaLN modulation ------------------------------------------
__global__ void k_ada(const float* __restrict__ siluc, const float* __restrict__ ada_w,
                      const float* __restrict__ ada_b, float* __restrict__ mod) {
    __shared__ float sc[512];
    int tid = threadIdx.x;  // 256
    for (int c = tid; c < 512; c += 256) sc[c] = siluc[c];
    __syncthreads();
    int warp = tid >> 5, lane = tid & 31;
    int m = blockIdx.x * 8 + warp;
    const float* wr = ada_w + (long)m * 512;
    float acc = 0.f;
    for (int k = lane; k < 512; k += 32) acc += sc[k] * wr[k];
#pragma unroll
    for (int off = 16; off; off >>= 1) acc += __shfl_xor_sync(0xffffffffu, acc, off);
    if (lane == 0) mod[m] = acc + ada_b[m];
}

// ---------------- LN + modulation -> split bf16 ------------------------------
__global__ void k_modln(const float* __restrict__ h, bf16* __restrict__ hn_h,
                        bf16* __restrict__ hn_l, const float* __restrict__ mod,
                        int sc_off, int sm_off) {
    int n = blockIdx.x;
    int tid = threadIdx.x;  // 128
    const float4* hp = (const float4*)(h + (long)n * CDIM);
    float4 x = hp[tid];
    float s = x.x + x.y + x.z + x.w;
    float sq = x.x * x.x + x.y * x.y + x.z * x.z + x.w * x.w;
#pragma unroll
    for (int off = 16; off; off >>= 1) {
        s += __shfl_xor_sync(0xffffffffu, s, off);
        sq += __shfl_xor_sync(0xffffffffu, sq, off);
    }
    __shared__ float rs[4], rq[4];
    int warp = tid >> 5;
    if ((tid & 31) == 0) { rs[warp] = s; rq[warp] = sq; }
    __syncthreads();
    float S = rs[0] + rs[1] + rs[2] + rs[3];
    float SQ = rq[0] + rq[1] + rq[2] + rq[3];
    float mean = S * (1.0f / 512.0f);
    float var = SQ * (1.0f / 512.0f) - mean * mean;
    float inv = rsqrtf(var + 1e-6f);
    int c = tid * 4;
    float4 scv = *(const float4*)(mod + sc_off + c);
    float4 smv = *(const float4*)(mod + sm_off + c);
    float o0 = (x.x - mean) * inv * (1.0f + scv.x) + smv.x;
    float o1 = (x.y - mean) * inv * (1.0f + scv.y) + smv.y;
    float o2 = (x.z - mean) * inv * (1.0f + scv.z) + smv.z;
    float o3 = (x.w - mean) * inv * (1.0f + scv.w) + smv.w;
    uint2 hv, lv;
    hv.x = pack_split(o0, o1, lv.x);
    hv.y = pack_split(o2, o3, lv.y);
    *(uint2*)(hn_h + (long)n * CDIM + c) = hv;
    *(uint2*)(hn_l + (long)n * CDIM + c) = lv;
}

// ---------------- output head ------------------------------------------------
__global__ void k_final(const float* __restrict__ h, const float* __restrict__ out_w,
                        const float* __restrict__ out_b, float* __restrict__ out) {
    int warp = threadIdx.x >> 5, lane = threadIdx.x & 31;
    int n = blockIdx.x * 8 + warp;
    const float* hp = h + (long)n * CDIM;
    float acc[8];
#pragma unroll
    for (int o = 0; o < 8; o++) acc[o] = 0.f;
    for (int c = lane; c < CDIM; c += 32) {
        float hv = hp[c];
#pragma unroll
        for (int o = 0; o < 8; o++) acc[o] += hv * out_w[o * CDIM + c];
    }
#pragma unroll
    for (int off = 16; off; off >>= 1)
#pragma unroll
        for (int o = 0; o < 8; o++) acc[o] += __shfl_xor_sync(0xffffffffu, acc[o], off);
    if (lane == 0)
#pragma unroll
        for (int o = 0; o < 8; o++) out[(long)n * 8 + o] = acc[o] + out_b[o];
}

// ---------------- launch ----------------------------------------------------
extern "C" void kernel_launch(void* const* d_in, const int* in_sizes, int n_in,
                              void* d_out, int out_size) {
    const float* feats  = (const float*)d_in[0];
    const int*   coords = (const int*)d_in[1];
    const float* t      = (const float*)d_in[2];
    const float* in_w   = (const float*)d_in[3];
    const float* in_b   = (const float*)d_in[4];
    const float* t_w1   = (const float*)d_in[5];
    const float* t_b1   = (const float*)d_in[6];
    const float* t_w2   = (const float*)d_in[7];
    const float* t_b2   = (const float*)d_in[8];
    const float* qkv_w  = (const float*)d_in[9];
    const float* qkv_b  = (const float*)d_in[10];
    const float* proj_w = (const float*)d_in[11];
    const float* proj_b = (const float*)d_in[12];
    const float* ada_w  = (const float*)d_in[13];
    const float* ada_b  = (const float*)d_in[14];
    const float* fc1_w  = (const float*)d_in[15];
    const float* fc1_b  = (const float*)d_in[16];
    const float* fc2_w  = (const float*)d_in[17];
    const float* fc2_b  = (const float*)d_in[18];
    const float* out_w  = (const float*)d_in[19];
    const float* out_b  = (const float*)d_in[20];
    float* out = (float*)d_out;

    float *p_h, *p_mod, *p_siluc;
    bf16 *p_hnh, *p_hnl, *p_qh, *p_ql, *p_ah, *p_al, *p_mh, *p_ml, *p_wh, *p_wl;
    cudaGetSymbolAddress((void**)&p_h, g_h);
    cudaGetSymbolAddress((void**)&p_mod, g_mod);
    cudaGetSymbolAddress((void**)&p_siluc, g_siluc);
    cudaGetSymbolAddress((void**)&p_hnh, g_hn_h);
    cudaGetSymbolAddress((void**)&p_hnl, g_hn_l);
    cudaGetSymbolAddress((void**)&p_qh, g_qkv_h);
    cudaGetSymbolAddress((void**)&p_ql, g_qkv_l);
    cudaGetSymbolAddress((void**)&p_ah, g_attn_h);
    cudaGetSymbolAddress((void**)&p_al, g_attn_l);
    cudaGetSymbolAddress((void**)&p_mh, g_mlp_h);
    cudaGetSymbolAddress((void**)&p_ml, g_mlp_l);
    cudaGetSymbolAddress((void**)&p_wh, g_wh);
    cudaGetSymbolAddress((void**)&p_wl, g_wl);

    const int GSM = 81920;
    const int ASM = 73728;
    cudaFuncSetAttribute(k_mma_gemm<0>, cudaFuncAttributeMaxDynamicSharedMemorySize, GSM);
    cudaFuncSetAttribute(k_mma_gemm<1>, cudaFuncAttributeMaxDynamicSharedMemorySize, GSM);
    cudaFuncSetAttribute(k_mma_gemm<2>, cudaFuncAttributeMaxDynamicSharedMemorySize, GSM);
    cudaFuncSetAttribute(k_attn_mma, cudaFuncAttributeMaxDynamicSharedMemorySize, ASM);

    // weight pre-split (runs every call; part of graph)
    k_split<<<(6291456 / 4 + 255) / 256, 256>>>(qkv_w, p_wh + OFF_QKV, p_wl + OFF_QKV, 6291456 / 4);
    k_split<<<(2097152 / 4 + 255) / 256, 256>>>(proj_w, p_wh + OFF_PROJ, p_wl + OFF_PROJ, 2097152 / 4);
    k_split<<<(8388608 / 4 + 255) / 256, 256>>>(fc1_w, p_wh + OFF_FC1, p_wl + OFF_FC1, 8388608 / 4);
    k_split<<<(8388608 / 4 + 255) / 256, 256>>>(fc2_w, p_wh + OFF_FC2, p_wl + OFF_FC2, 8388608 / 4);

    k_init<<<NTOK, 256>>>(feats, coords, in_w, in_b, p_h);
    k_tembed<<<1, 256>>>(t, t_w1, t_b1, t_w2, t_b2, p_siluc);

    for (int i = 0; i < 8; i++) {
        int shift = (i & 1) * 512;
        k_ada<<<384, 256>>>(p_siluc, ada_w + (long)i * 3072 * 512, ada_b + (long)i * 3072, p_mod);
        // attention branch
        k_modln<<<NTOK, 128>>>(p_h, p_hnh, p_hnl, p_mod, 512, 0);
        k_mma_gemm<0><<<dim3(12, 128), 256, GSM>>>(
            p_hnh, p_hnl, p_wh + OFF_QKV + (long)i * 786432, p_wl + OFF_QKV + (long)i * 786432,
            qkv_b + (long)i * 1536, nullptr, p_qh, p_ql, nullptr, 512, 1536);
        k_attn_mma<<<dim3(8, 8, 16), 256, ASM>>>(p_qh, p_ql, p_ah, p_al, shift);
        k_mma_gemm<2><<<dim3(4, 128), 256, GSM>>>(
            p_ah, p_al, p_wh + OFF_PROJ + (long)i * 262144, p_wl + OFF_PROJ + (long)i * 262144,
            proj_b + (long)i * 512, p_h, nullptr, nullptr, p_mod + 1024, 512, 512);
        // mlp branch
        k_modln<<<NTOK, 128>>>(p_h, p_hnh, p_hnl, p_mod, 2048, 1536);
        k_mma_gemm<1><<<dim3(16, 128), 256, GSM>>>(
            p_hnh, p_hnl, p_wh + OFF_FC1 + (long)i * 1048576, p_wl + OFF_FC1 + (long)i * 1048576,
            fc1_b + (long)i * 2048, nullptr, p_mh, p_ml, nullptr, 512, 2048);
        k_mma_gemm<2><<<dim3(4, 128), 256, GSM>>>(
            p_mh, p_ml, p_wh + OFF_FC2 + (long)i * 1048576, p_wl + OFF_FC2 + (long)i * 1048576,
            fc2_b + (long)i * 512, p_h, nullptr, nullptr, p_mod + 2560, 2048, 512);
    }

    k_final<<<2048, 256>>>(p_h, out_w, out_b, out);
}